// round 3
// baseline (speedup 1.0000x reference)
// v3 — identical compute to v2; resubmission after two broker-side container
// failures (no kernel-attributable diagnostics; see round notes).
#include <cuda_runtime.h>

// Problem constants (fixed shapes per reference)
#define NN 100000
#define EE 1600000
#define GG 256
#define D_EMB 16
#define D_HID 32

// Scan config
#define SCAN_BS 512
#define SCAN_NB ((NN + SCAN_BS - 1) / SCAN_BS)   // 196

// ---------------- device scratch (static, no allocation) ----------------
__device__ float g_x[NN * D_HID];      // feature buffer A ([N,16] for embed, then [N,32])
__device__ float g_h[NN * D_HID];      // feature buffer B (linear-transform output)
__device__ float g_dinv[NN];           // deg^-1/2
__device__ int   g_count[NN];          // in-degree counts (excl. self loop)
__device__ int   g_off[NN];            // CSR row offsets (exclusive prefix of counts)
__device__ int   g_cur[NN];            // scatter cursors
__device__ int   g_csrc[EE];           // CSR src indices grouped by dst
__device__ float g_pool[2 * GG * D_HID];
__device__ float g_cnt[2 * GG];
__device__ int   g_bsum[SCAN_BS];      // block sums for the scan (196 <= 512)

// ---------------- kernels ----------------

__global__ void k_zero_side() {
    int i = blockIdx.x * blockDim.x + threadIdx.x;
    if (i < NN) { g_count[i] = 0; g_cur[i] = 0; }
}

__global__ void k_zero_pool() {
    int i = blockIdx.x * blockDim.x + threadIdx.x;
    if (i < 2 * GG * D_HID) g_pool[i] = 0.f;
    if (i < 2 * GG) g_cnt[i] = 0.f;
}

__global__ void k_count(const int* __restrict__ ei) {
    int e = blockIdx.x * blockDim.x + threadIdx.x;
    if (e < EE) atomicAdd(&g_count[__ldg(&ei[EE + e])], 1);
}

__global__ void k_dinv() {
    int n = blockIdx.x * blockDim.x + threadIdx.x;
    if (n < NN) g_dinv[n] = rsqrtf((float)(g_count[n] + 1));  // +1 self loop, always >=1
}

// Exclusive scan of g_count -> g_off  (3 kernels)
__global__ void k_scan1() {
    __shared__ int s[SCAN_BS];
    int t = threadIdx.x;
    int i = blockIdx.x * SCAN_BS + t;
    int v = (i < NN) ? g_count[i] : 0;
    s[t] = v;
    __syncthreads();
    for (int d = 1; d < SCAN_BS; d <<= 1) {
        int u = (t >= d) ? s[t - d] : 0;
        __syncthreads();
        s[t] += u;
        __syncthreads();
    }
    if (i < NN) g_off[i] = s[t] - v;            // exclusive within block
    if (t == SCAN_BS - 1) g_bsum[blockIdx.x] = s[t];
}

__global__ void k_scan2() {
    __shared__ int s[SCAN_BS];
    int t = threadIdx.x;
    int v = (t < SCAN_NB) ? g_bsum[t] : 0;
    s[t] = v;
    __syncthreads();
    for (int d = 1; d < SCAN_BS; d <<= 1) {
        int u = (t >= d) ? s[t - d] : 0;
        __syncthreads();
        s[t] += u;
        __syncthreads();
    }
    g_bsum[t] = s[t] - v;                        // exclusive block offsets
}

__global__ void k_scan3() {
    int i = blockIdx.x * SCAN_BS + threadIdx.x;
    if (i < NN) g_off[i] += g_bsum[blockIdx.x];
}

__global__ void k_scatter(const int* __restrict__ ei) {
    int e = blockIdx.x * blockDim.x + threadIdx.x;
    if (e < EE) {
        int src = __ldg(&ei[e]);
        int dst = __ldg(&ei[EE + e]);
        int p = atomicAdd(&g_cur[dst], 1);
        g_csrc[g_off[dst] + p] = src;
    }
}

// x[n,:16] = emb[gate_ids[n]] + params[n]*pW + pb
__global__ void k_embed(const int* __restrict__ gid, const float* __restrict__ par,
                        const float* __restrict__ emb, const float* __restrict__ pW,
                        const float* __restrict__ pb) {
    int i = blockIdx.x * blockDim.x + threadIdx.x;
    if (i < NN * D_EMB) {
        int n = i >> 4, f = i & 15;
        g_x[i] = __ldg(&emb[gid[n] * D_EMB + f]) + __ldg(&par[n]) * __ldg(&pW[f]) + __ldg(&pb[f]);
    }
}

// h = x @ W1 :  [N,16] x [16,32] -> [N,32]  (warp per node, lane = out feature)
__global__ void __launch_bounds__(256) k_matvec16(const float* __restrict__ W) {
    int gt = blockIdx.x * blockDim.x + threadIdx.x;
    int n = gt >> 5, lane = gt & 31;
    if (n >= NN) return;
    float xv = (lane < D_EMB) ? g_x[n * D_EMB + lane] : 0.f;
    float acc = 0.f;
#pragma unroll
    for (int k = 0; k < D_EMB; k++)
        acc = fmaf(__shfl_sync(0xffffffffu, xv, k), __ldg(&W[k * D_HID + lane]), acc);
    g_h[n * D_HID + lane] = acc;
}

// h = x @ W2 :  [N,32] x [32,32] -> [N,32]
__global__ void __launch_bounds__(256) k_matvec32(const float* __restrict__ W) {
    __shared__ float sW[D_HID * D_HID];
    for (int j = threadIdx.x; j < D_HID * D_HID; j += blockDim.x) sW[j] = W[j];
    __syncthreads();
    int gt = blockIdx.x * blockDim.x + threadIdx.x;
    int n = gt >> 5, lane = gt & 31;
    if (n >= NN) return;
    float xv = g_x[n * D_HID + lane];
    float acc = 0.f;
#pragma unroll
    for (int k = 0; k < D_HID; k++)
        acc = fmaf(__shfl_sync(0xffffffffu, xv, k), sW[k * D_HID + lane], acc);
    g_h[n * D_HID + lane] = acc;
}

// out[n] = relu( dinv[n] * ( h[n]*dinv[n] + sum_{e in CSR row n} h[src_e]*dinv[src_e] ) + b )
// warp per dst node, lane = feature.
__global__ void __launch_bounds__(256) k_aggregate(const float* __restrict__ b) {
    int gt = blockIdx.x * blockDim.x + threadIdx.x;
    int n = gt >> 5, lane = gt & 31;
    if (n >= NN) return;
    float dn = g_dinv[n];
    float acc = g_h[n * D_HID + lane] * dn;      // self loop (dn applied again at end)
    int beg = g_off[n];
    int end = beg + g_count[n];
    int e = beg;
    for (; e + 4 <= end; e += 4) {
        int s0 = __ldg(&g_csrc[e]);
        int s1 = __ldg(&g_csrc[e + 1]);
        int s2 = __ldg(&g_csrc[e + 2]);
        int s3 = __ldg(&g_csrc[e + 3]);
        float d0 = __ldg(&g_dinv[s0]), d1 = __ldg(&g_dinv[s1]);
        float d2 = __ldg(&g_dinv[s2]), d3 = __ldg(&g_dinv[s3]);
        float h0 = __ldg(&g_h[s0 * D_HID + lane]);
        float h1 = __ldg(&g_h[s1 * D_HID + lane]);
        float h2 = __ldg(&g_h[s2 * D_HID + lane]);
        float h3 = __ldg(&g_h[s3 * D_HID + lane]);
        acc = fmaf(h0, d0, acc);
        acc = fmaf(h1, d1, acc);
        acc = fmaf(h2, d2, acc);
        acc = fmaf(h3, d3, acc);
    }
    for (; e < end; e++) {
        int s = __ldg(&g_csrc[e]);
        acc = fmaf(__ldg(&g_h[s * D_HID + lane]), __ldg(&g_dinv[s]), acc);
    }
    float o = fmaf(acc, dn, __ldg(&b[lane]));
    g_x[n * D_HID + lane] = fmaxf(o, 0.f);
}

// segment sum + counts into pool[side]
__global__ void __launch_bounds__(256) k_pool(const int* __restrict__ batch, int side) {
    int gt = blockIdx.x * blockDim.x + threadIdx.x;
    int n = gt >> 5, lane = gt & 31;
    if (n >= NN) return;
    int g = __ldg(&batch[n]);
    atomicAdd(&g_pool[(side * GG + g) * D_HID + lane], g_x[n * D_HID + lane]);
    if (lane == 0) atomicAdd(&g_cnt[side * GG + g], 1.f);
}

// final MLP: [G,64] -> relu([G,32]) -> [G,1]   warp per graph, lane = hidden unit
__global__ void __launch_bounds__(256) k_final(const float* __restrict__ fW1,
                                               const float* __restrict__ fb1,
                                               const float* __restrict__ fW2,
                                               const float* __restrict__ fb2,
                                               float* __restrict__ out) {
    int gt = blockIdx.x * blockDim.x + threadIdx.x;
    int g = gt >> 5, lane = gt & 31;
    if (g >= GG) return;
    float cl = 1.f / fmaxf(g_cnt[g], 1.f);
    float cr = 1.f / fmaxf(g_cnt[GG + g], 1.f);
    float pl = g_pool[g * D_HID + lane] * cl;
    float pr = g_pool[(GG + g) * D_HID + lane] * cr;
    float acc = __ldg(&fb1[lane]);
#pragma unroll
    for (int k = 0; k < D_HID; k++) {
        acc = fmaf(__shfl_sync(0xffffffffu, pl, k), __ldg(&fW1[k * D_HID + lane]), acc);
        acc = fmaf(__shfl_sync(0xffffffffu, pr, k), __ldg(&fW1[(D_HID + k) * D_HID + lane]), acc);
    }
    float v = fmaxf(acc, 0.f) * __ldg(&fW2[lane]);
#pragma unroll
    for (int o = 16; o > 0; o >>= 1) v += __shfl_down_sync(0xffffffffu, v, o);
    if (lane == 0) out[g] = v + __ldg(&fb2[0]);
}

// ---------------- launch ----------------

static void run_side(const int* gid, const float* par, const int* ei, const int* batch,
                     const float* emb, const float* pW, const float* pb,
                     const float* W1, const float* b1,
                     const float* W2, const float* b2, int side) {
    const int TB = 256;
    k_zero_side<<<(NN + TB - 1) / TB, TB>>>();
    k_count<<<(EE + TB - 1) / TB, TB>>>(ei);
    k_dinv<<<(NN + TB - 1) / TB, TB>>>();
    k_scan1<<<SCAN_NB, SCAN_BS>>>();
    k_scan2<<<1, SCAN_BS>>>();
    k_scan3<<<SCAN_NB, SCAN_BS>>>();
    k_scatter<<<(EE + TB - 1) / TB, TB>>>(ei);
    k_embed<<<(NN * D_EMB + TB - 1) / TB, TB>>>(gid, par, emb, pW, pb);
    const int WBLK = (NN * 32 + TB - 1) / TB;   // warp-per-node kernels
    k_matvec16<<<WBLK, TB>>>(W1);
    k_aggregate<<<WBLK, TB>>>(b1);
    k_matvec32<<<WBLK, TB>>>(W2);
    k_aggregate<<<WBLK, TB>>>(b2);
    k_pool<<<WBLK, TB>>>(batch, side);
}

extern "C" void kernel_launch(void* const* d_in, const int* in_sizes, int n_in,
                              void* d_out, int out_size) {
    const int*   lhs_gid = (const int*)d_in[0];
    const float* lhs_par = (const float*)d_in[1];
    const int*   lhs_ei  = (const int*)d_in[2];
    const int*   lhs_b   = (const int*)d_in[3];
    const int*   rhs_gid = (const int*)d_in[4];
    const float* rhs_par = (const float*)d_in[5];
    const int*   rhs_ei  = (const int*)d_in[6];
    const int*   rhs_b   = (const int*)d_in[7];
    const float* emb = (const float*)d_in[8];
    const float* pW  = (const float*)d_in[9];
    const float* pb  = (const float*)d_in[10];
    const float* W1  = (const float*)d_in[11];
    const float* b1  = (const float*)d_in[12];
    const float* W2  = (const float*)d_in[13];
    const float* b2  = (const float*)d_in[14];
    const float* fW1 = (const float*)d_in[15];
    const float* fb1 = (const float*)d_in[16];
    const float* fW2 = (const float*)d_in[17];
    const float* fb2 = (const float*)d_in[18];
    float* out = (float*)d_out;

    k_zero_pool<<<(2 * GG * D_HID + 255) / 256, 256>>>();
    run_side(lhs_gid, lhs_par, lhs_ei, lhs_b, emb, pW, pb, W1, b1, W2, b2, 0);
    run_side(rhs_gid, rhs_par, rhs_ei, rhs_b, emb, pW, pb, W1, b1, W2, b2, 1);
    k_final<<<(GG * 32 + 255) / 256, 256>>>(fW1, fb1, fW2, fb2, out);
}

// round 4
// speedup vs baseline: 1.1284x; 1.1284x over previous
// v4 — fused pipeline: pre-scaled rows (no per-edge dinv gather), embed+mv16,
// agg+mv32, agg+pool fusions, both sides merged into single kernels (10 launches).
#include <cuda_runtime.h>

#define NN 100000
#define EE 1600000
#define GG 256
#define D_EMB 16
#define D_HID 32

#define SCAN_BS 512
#define SCAN_NB ((NN + SCAN_BS - 1) / SCAN_BS)   // 196

// ---------------- device scratch ----------------
__device__ float g_h[2 * NN * D_HID];    // layer input rows, pre-scaled by dinv[src]
__device__ float g_h2[2 * NN * D_HID];   // next-layer rows, pre-scaled
__device__ float g_dinv[2 * NN];
__device__ int   g_count[2 * NN];
__device__ int   g_off[2 * NN];          // absolute CSR offsets (incl. side*EE base)
__device__ int   g_cur[2 * NN];
__device__ int   g_csrc[2 * EE];
__device__ float g_pool[2 * GG * D_HID];
__device__ float g_cnt[2 * GG];
__device__ int   g_bsum[2 * SCAN_BS];

// ---------------- kernels ----------------

__global__ void k_zero() {
    int i = blockIdx.x * blockDim.x + threadIdx.x;
    if (i < 2 * NN) g_count[i] = 0;
    if (i < 2 * GG * D_HID) g_pool[i] = 0.f;
    if (i < 2 * GG) g_cnt[i] = 0.f;
}

__global__ void k_count(const int* __restrict__ ei0, const int* __restrict__ ei1) {
    int e = blockIdx.x * blockDim.x + threadIdx.x;
    if (e >= 2 * EE) return;
    int side = e >= EE;
    const int* ei = side ? ei1 : ei0;
    int el = e - side * EE;
    int dst = __ldg(&ei[EE + el]);
    atomicAdd(&g_count[side * NN + dst], 1);
}

// per-side exclusive scan over counts; also computes dinv
__global__ void k_scan1() {
    __shared__ int s[SCAN_BS];
    int side = blockIdx.x / SCAN_NB;
    int blk  = blockIdx.x % SCAN_NB;
    int t = threadIdx.x;
    int li = blk * SCAN_BS + t;                 // index within side
    int i  = side * NN + li;
    int v = (li < NN) ? g_count[i] : 0;
    if (li < NN) g_dinv[i] = rsqrtf((float)(v + 1));
    s[t] = v;
    __syncthreads();
    for (int d = 1; d < SCAN_BS; d <<= 1) {
        int u = (t >= d) ? s[t - d] : 0;
        __syncthreads();
        s[t] += u;
        __syncthreads();
    }
    if (li < NN) g_off[i] = s[t] - v;           // exclusive within block
    if (t == SCAN_BS - 1) g_bsum[side * SCAN_BS + blk] = s[t];
}

__global__ void k_scan2() {      // 2 blocks, one per side
    __shared__ int s[SCAN_BS];
    int side = blockIdx.x;
    int t = threadIdx.x;
    int v = (t < SCAN_NB) ? g_bsum[side * SCAN_BS + t] : 0;
    s[t] = v;
    __syncthreads();
    for (int d = 1; d < SCAN_BS; d <<= 1) {
        int u = (t >= d) ? s[t - d] : 0;
        __syncthreads();
        s[t] += u;
        __syncthreads();
    }
    g_bsum[side * SCAN_BS + t] = s[t] - v;      // exclusive block offsets
}

__global__ void k_scan3() {      // finalize absolute offsets, init cursors
    int side = blockIdx.x / SCAN_NB;
    int blk  = blockIdx.x % SCAN_NB;
    int li = blk * SCAN_BS + threadIdx.x;
    if (li < NN) {
        int i = side * NN + li;
        int o = g_off[i] + g_bsum[side * SCAN_BS + blk] + side * EE;
        g_off[i] = o;
        g_cur[i] = o;
    }
}

__global__ void k_scatter(const int* __restrict__ ei0, const int* __restrict__ ei1) {
    int e = blockIdx.x * blockDim.x + threadIdx.x;
    if (e >= 2 * EE) return;
    int side = e >= EE;
    const int* ei = side ? ei1 : ei0;
    int el = e - side * EE;
    int src = __ldg(&ei[el]);
    int dst = __ldg(&ei[EE + el]);
    int p = atomicAdd(&g_cur[side * NN + dst], 1);
    g_csrc[p] = src;                             // local node id
}

// fused: x = emb[gid] + par*pW + pb ;  h' = (x @ W1) * dinv[n]
// warp per node (2*NN warps); lane = output feature
__global__ void __launch_bounds__(256) k_embed_mv16(
        const int* __restrict__ gid0, const float* __restrict__ par0,
        const int* __restrict__ gid1, const float* __restrict__ par1,
        const float* __restrict__ emb, const float* __restrict__ pW,
        const float* __restrict__ pb, const float* __restrict__ W1) {
    int gt = blockIdx.x * blockDim.x + threadIdx.x;
    int nid = gt >> 5, lane = gt & 31;
    if (nid >= 2 * NN) return;
    int side = nid >= NN;
    int n = nid - side * NN;
    const int*   gid = side ? gid1 : gid0;
    const float* par = side ? par1 : par0;
    int   g = __ldg(&gid[n]);
    float p = __ldg(&par[n]);
    float xv = 0.f;
    if (lane < D_EMB)
        xv = __ldg(&emb[g * D_EMB + lane]) + p * __ldg(&pW[lane]) + __ldg(&pb[lane]);
    float acc = 0.f;
#pragma unroll
    for (int k = 0; k < D_EMB; k++)
        acc = fmaf(__shfl_sync(0xffffffffu, xv, k), __ldg(&W1[k * D_HID + lane]), acc);
    g_h[nid * D_HID + lane] = acc * g_dinv[nid];
}

// fused: y = relu(dinv*(self + Σ h'[src]) + b1);  h2' = (y @ W2) * dinv
__global__ void __launch_bounds__(256) k_agg_mv32(const float* __restrict__ b1,
                                                  const float* __restrict__ W2) {
    __shared__ float sW[D_HID * D_HID];
    for (int j = threadIdx.x; j < D_HID * D_HID; j += blockDim.x) sW[j] = W2[j];
    __syncthreads();
    int gt = blockIdx.x * blockDim.x + threadIdx.x;
    int nid = gt >> 5, lane = gt & 31;
    if (nid >= 2 * NN) return;
    int side = nid >= NN;
    int srow = side * NN;                        // src row base for this side
    float dn = g_dinv[nid];
    float acc = g_h[nid * D_HID + lane];         // self loop (pre-scaled)
    int e = g_off[nid];
    int end = e + g_count[nid];
    for (; e + 4 <= end; e += 4) {
        int s0 = __ldg(&g_csrc[e]),     s1 = __ldg(&g_csrc[e + 1]);
        int s2 = __ldg(&g_csrc[e + 2]), s3 = __ldg(&g_csrc[e + 3]);
        float h0 = __ldg(&g_h[(srow + s0) * D_HID + lane]);
        float h1 = __ldg(&g_h[(srow + s1) * D_HID + lane]);
        float h2 = __ldg(&g_h[(srow + s2) * D_HID + lane]);
        float h3 = __ldg(&g_h[(srow + s3) * D_HID + lane]);
        acc += h0 + h1 + h2 + h3;
    }
    for (; e < end; e++)
        acc += __ldg(&g_h[(srow + __ldg(&g_csrc[e])) * D_HID + lane]);
    float y = fmaxf(fmaf(acc, dn, __ldg(&b1[lane])), 0.f);
    // matvec32 epilogue: z[lane] = sum_k y[k] * W2[k][lane]
    float z = 0.f;
#pragma unroll
    for (int k = 0; k < D_HID; k++)
        z = fmaf(__shfl_sync(0xffffffffu, y, k), sW[k * D_HID + lane], z);
    g_h2[nid * D_HID + lane] = z * dn;
}

// fused: y = relu(dinv*(self + Σ h2'[src]) + b2);  pool += y
__global__ void __launch_bounds__(256) k_agg_pool(const float* __restrict__ b2,
                                                  const int* __restrict__ bat0,
                                                  const int* __restrict__ bat1) {
    int gt = blockIdx.x * blockDim.x + threadIdx.x;
    int nid = gt >> 5, lane = gt & 31;
    if (nid >= 2 * NN) return;
    int side = nid >= NN;
    int n = nid - side * NN;
    int srow = side * NN;
    float dn = g_dinv[nid];
    float acc = g_h2[nid * D_HID + lane];
    int e = g_off[nid];
    int end = e + g_count[nid];
    for (; e + 4 <= end; e += 4) {
        int s0 = __ldg(&g_csrc[e]),     s1 = __ldg(&g_csrc[e + 1]);
        int s2 = __ldg(&g_csrc[e + 2]), s3 = __ldg(&g_csrc[e + 3]);
        float h0 = __ldg(&g_h2[(srow + s0) * D_HID + lane]);
        float h1 = __ldg(&g_h2[(srow + s1) * D_HID + lane]);
        float h2 = __ldg(&g_h2[(srow + s2) * D_HID + lane]);
        float h3 = __ldg(&g_h2[(srow + s3) * D_HID + lane]);
        acc += h0 + h1 + h2 + h3;
    }
    for (; e < end; e++)
        acc += __ldg(&g_h2[(srow + __ldg(&g_csrc[e])) * D_HID + lane]);
    float y = fmaxf(fmaf(acc, dn, __ldg(&b2[lane])), 0.f);
    const int* bat = side ? bat1 : bat0;
    int g = __ldg(&bat[n]);
    atomicAdd(&g_pool[(side * GG + g) * D_HID + lane], y);
    if (lane == 0) atomicAdd(&g_cnt[side * GG + g], 1.f);
}

// final MLP: [G,64] -> relu([G,32]) -> [G,1]   warp per graph
__global__ void __launch_bounds__(256) k_final(const float* __restrict__ fW1,
                                               const float* __restrict__ fb1,
                                               const float* __restrict__ fW2,
                                               const float* __restrict__ fb2,
                                               float* __restrict__ out) {
    int gt = blockIdx.x * blockDim.x + threadIdx.x;
    int g = gt >> 5, lane = gt & 31;
    if (g >= GG) return;
    float cl = 1.f / fmaxf(g_cnt[g], 1.f);
    float cr = 1.f / fmaxf(g_cnt[GG + g], 1.f);
    float pl = g_pool[g * D_HID + lane] * cl;
    float pr = g_pool[(GG + g) * D_HID + lane] * cr;
    float acc = __ldg(&fb1[lane]);
#pragma unroll
    for (int k = 0; k < D_HID; k++) {
        acc = fmaf(__shfl_sync(0xffffffffu, pl, k), __ldg(&fW1[k * D_HID + lane]), acc);
        acc = fmaf(__shfl_sync(0xffffffffu, pr, k), __ldg(&fW1[(D_HID + k) * D_HID + lane]), acc);
    }
    float v = fmaxf(acc, 0.f) * __ldg(&fW2[lane]);
#pragma unroll
    for (int o = 16; o > 0; o >>= 1) v += __shfl_down_sync(0xffffffffu, v, o);
    if (lane == 0) out[g] = v + __ldg(&fb2[0]);
}

// ---------------- launch ----------------

extern "C" void kernel_launch(void* const* d_in, const int* in_sizes, int n_in,
                              void* d_out, int out_size) {
    const int*   lhs_gid = (const int*)d_in[0];
    const float* lhs_par = (const float*)d_in[1];
    const int*   lhs_ei  = (const int*)d_in[2];
    const int*   lhs_b   = (const int*)d_in[3];
    const int*   rhs_gid = (const int*)d_in[4];
    const float* rhs_par = (const float*)d_in[5];
    const int*   rhs_ei  = (const int*)d_in[6];
    const int*   rhs_b   = (const int*)d_in[7];
    const float* emb = (const float*)d_in[8];
    const float* pW  = (const float*)d_in[9];
    const float* pb  = (const float*)d_in[10];
    const float* W1  = (const float*)d_in[11];
    const float* b1  = (const float*)d_in[12];
    const float* W2  = (const float*)d_in[13];
    const float* b2  = (const float*)d_in[14];
    const float* fW1 = (const float*)d_in[15];
    const float* fb1 = (const float*)d_in[16];
    const float* fW2 = (const float*)d_in[17];
    const float* fb2 = (const float*)d_in[18];
    float* out = (float*)d_out;

    const int TB = 256;
    k_zero<<<(2 * NN + TB - 1) / TB, TB>>>();
    k_count<<<(2 * EE + TB - 1) / TB, TB>>>(lhs_ei, rhs_ei);
    k_scan1<<<2 * SCAN_NB, SCAN_BS>>>();
    k_scan2<<<2, SCAN_BS>>>();
    k_scan3<<<2 * SCAN_NB, SCAN_BS>>>();
    k_scatter<<<(2 * EE + TB - 1) / TB, TB>>>(lhs_ei, rhs_ei);

    const int WBLK = (2 * NN * 32 + TB - 1) / TB;   // warp-per-node kernels
    k_embed_mv16<<<WBLK, TB>>>(lhs_gid, lhs_par, rhs_gid, rhs_par, emb, pW, pb, W1);
    k_agg_mv32<<<WBLK, TB>>>(b1, W2);
    k_agg_pool<<<WBLK, TB>>>(b2, lhs_b, rhs_b);
    k_final<<<(GG * 32 + 255) / 256, 256>>>(fW1, fb1, fW2, fb2, out);
}

// round 5
// speedup vs baseline: 1.1467x; 1.0162x over previous
// v5 — fp16 feature-row storage (halves gather traffic), 8-deep edge unroll.
#include <cuda_runtime.h>
#include <cuda_fp16.h>

#define NN 100000
#define EE 1600000
#define GG 256
#define D_EMB 16
#define D_HID 32

#define SCAN_BS 512
#define SCAN_NB ((NN + SCAN_BS - 1) / SCAN_BS)   // 196

// ---------------- device scratch ----------------
__device__ __half g_h[2 * NN * D_HID];    // layer rows, pre-scaled by dinv[src], fp16
__device__ __half g_h2[2 * NN * D_HID];
__device__ float  g_dinv[2 * NN];
__device__ int    g_count[2 * NN];
__device__ int    g_off[2 * NN];          // absolute CSR offsets (incl. side*EE base)
__device__ int    g_cur[2 * NN];
__device__ int    g_csrc[2 * EE];
__device__ float  g_pool[2 * GG * D_HID];
__device__ float  g_cnt[2 * GG];
__device__ int    g_bsum[2 * SCAN_BS];

// ---------------- kernels ----------------

__global__ void k_zero() {
    int i = blockIdx.x * blockDim.x + threadIdx.x;
    if (i < 2 * NN) g_count[i] = 0;
    if (i < 2 * GG * D_HID) g_pool[i] = 0.f;
    if (i < 2 * GG) g_cnt[i] = 0.f;
}

__global__ void k_count(const int* __restrict__ ei0, const int* __restrict__ ei1) {
    int e = blockIdx.x * blockDim.x + threadIdx.x;
    if (e >= 2 * EE) return;
    int side = e >= EE;
    const int* ei = side ? ei1 : ei0;
    int el = e - side * EE;
    int dst = __ldg(&ei[EE + el]);
    atomicAdd(&g_count[side * NN + dst], 1);
}

__global__ void k_scan1() {
    __shared__ int s[SCAN_BS];
    int side = blockIdx.x / SCAN_NB;
    int blk  = blockIdx.x % SCAN_NB;
    int t = threadIdx.x;
    int li = blk * SCAN_BS + t;
    int i  = side * NN + li;
    int v = (li < NN) ? g_count[i] : 0;
    if (li < NN) g_dinv[i] = rsqrtf((float)(v + 1));
    s[t] = v;
    __syncthreads();
    for (int d = 1; d < SCAN_BS; d <<= 1) {
        int u = (t >= d) ? s[t - d] : 0;
        __syncthreads();
        s[t] += u;
        __syncthreads();
    }
    if (li < NN) g_off[i] = s[t] - v;
    if (t == SCAN_BS - 1) g_bsum[side * SCAN_BS + blk] = s[t];
}

__global__ void k_scan2() {      // 2 blocks, one per side
    __shared__ int s[SCAN_BS];
    int side = blockIdx.x;
    int t = threadIdx.x;
    int v = (t < SCAN_NB) ? g_bsum[side * SCAN_BS + t] : 0;
    s[t] = v;
    __syncthreads();
    for (int d = 1; d < SCAN_BS; d <<= 1) {
        int u = (t >= d) ? s[t - d] : 0;
        __syncthreads();
        s[t] += u;
        __syncthreads();
    }
    g_bsum[side * SCAN_BS + t] = s[t] - v;
}

__global__ void k_scan3() {
    int side = blockIdx.x / SCAN_NB;
    int blk  = blockIdx.x % SCAN_NB;
    int li = blk * SCAN_BS + threadIdx.x;
    if (li < NN) {
        int i = side * NN + li;
        int o = g_off[i] + g_bsum[side * SCAN_BS + blk] + side * EE;
        g_off[i] = o;
        g_cur[i] = o;
    }
}

__global__ void k_scatter(const int* __restrict__ ei0, const int* __restrict__ ei1) {
    int e = blockIdx.x * blockDim.x + threadIdx.x;
    if (e >= 2 * EE) return;
    int side = e >= EE;
    const int* ei = side ? ei1 : ei0;
    int el = e - side * EE;
    int src = __ldg(&ei[el]);
    int dst = __ldg(&ei[EE + el]);
    int p = atomicAdd(&g_cur[side * NN + dst], 1);
    g_csrc[p] = src;
}

// fused: x = emb[gid]+par*pW+pb ; h' = (x @ W1)*dinv  -> fp16
__global__ void __launch_bounds__(256) k_embed_mv16(
        const int* __restrict__ gid0, const float* __restrict__ par0,
        const int* __restrict__ gid1, const float* __restrict__ par1,
        const float* __restrict__ emb, const float* __restrict__ pW,
        const float* __restrict__ pb, const float* __restrict__ W1) {
    int gt = blockIdx.x * blockDim.x + threadIdx.x;
    int nid = gt >> 5, lane = gt & 31;
    if (nid >= 2 * NN) return;
    int side = nid >= NN;
    int n = nid - side * NN;
    const int*   gid = side ? gid1 : gid0;
    const float* par = side ? par1 : par0;
    int   g = __ldg(&gid[n]);
    float p = __ldg(&par[n]);
    float xv = 0.f;
    if (lane < D_EMB)
        xv = __ldg(&emb[g * D_EMB + lane]) + p * __ldg(&pW[lane]) + __ldg(&pb[lane]);
    float acc = 0.f;
#pragma unroll
    for (int k = 0; k < D_EMB; k++)
        acc = fmaf(__shfl_sync(0xffffffffu, xv, k), __ldg(&W1[k * D_HID + lane]), acc);
    g_h[nid * D_HID + lane] = __float2half(acc * g_dinv[nid]);
}

// fused: y = relu(dinv*(self + Σ h'[src]) + b1);  h2' = (y @ W2)*dinv -> fp16
__global__ void __launch_bounds__(256) k_agg_mv32(const float* __restrict__ b1,
                                                  const float* __restrict__ W2) {
    __shared__ float sW[D_HID * D_HID];
    for (int j = threadIdx.x; j < D_HID * D_HID; j += blockDim.x) sW[j] = W2[j];
    __syncthreads();
    int gt = blockIdx.x * blockDim.x + threadIdx.x;
    int nid = gt >> 5, lane = gt & 31;
    if (nid >= 2 * NN) return;
    int side = nid >= NN;
    int srow = side * NN;
    float dn = g_dinv[nid];
    float acc = __half2float(g_h[nid * D_HID + lane]);   // self loop (pre-scaled)
    int e = g_off[nid];
    int end = e + g_count[nid];
    for (; e + 8 <= end; e += 8) {
        int s0 = __ldg(&g_csrc[e]),     s1 = __ldg(&g_csrc[e + 1]);
        int s2 = __ldg(&g_csrc[e + 2]), s3 = __ldg(&g_csrc[e + 3]);
        int s4 = __ldg(&g_csrc[e + 4]), s5 = __ldg(&g_csrc[e + 5]);
        int s6 = __ldg(&g_csrc[e + 6]), s7 = __ldg(&g_csrc[e + 7]);
        float h0 = __half2float(__ldg(&g_h[(srow + s0) * D_HID + lane]));
        float h1 = __half2float(__ldg(&g_h[(srow + s1) * D_HID + lane]));
        float h2 = __half2float(__ldg(&g_h[(srow + s2) * D_HID + lane]));
        float h3 = __half2float(__ldg(&g_h[(srow + s3) * D_HID + lane]));
        float h4 = __half2float(__ldg(&g_h[(srow + s4) * D_HID + lane]));
        float h5 = __half2float(__ldg(&g_h[(srow + s5) * D_HID + lane]));
        float h6 = __half2float(__ldg(&g_h[(srow + s6) * D_HID + lane]));
        float h7 = __half2float(__ldg(&g_h[(srow + s7) * D_HID + lane]));
        acc += ((h0 + h1) + (h2 + h3)) + ((h4 + h5) + (h6 + h7));
    }
    for (; e < end; e++)
        acc += __half2float(__ldg(&g_h[(srow + __ldg(&g_csrc[e])) * D_HID + lane]));
    float y = fmaxf(fmaf(acc, dn, __ldg(&b1[lane])), 0.f);
    float z = 0.f;
#pragma unroll
    for (int k = 0; k < D_HID; k++)
        z = fmaf(__shfl_sync(0xffffffffu, y, k), sW[k * D_HID + lane], z);
    g_h2[nid * D_HID + lane] = __float2half(z * dn);
}

// fused: y = relu(dinv*(self + Σ h2'[src]) + b2);  pool += y
__global__ void __launch_bounds__(256) k_agg_pool(const float* __restrict__ b2,
                                                  const int* __restrict__ bat0,
                                                  const int* __restrict__ bat1) {
    int gt = blockIdx.x * blockDim.x + threadIdx.x;
    int nid = gt >> 5, lane = gt & 31;
    if (nid >= 2 * NN) return;
    int side = nid >= NN;
    int n = nid - side * NN;
    int srow = side * NN;
    float dn = g_dinv[nid];
    float acc = __half2float(g_h2[nid * D_HID + lane]);
    int e = g_off[nid];
    int end = e + g_count[nid];
    for (; e + 8 <= end; e += 8) {
        int s0 = __ldg(&g_csrc[e]),     s1 = __ldg(&g_csrc[e + 1]);
        int s2 = __ldg(&g_csrc[e + 2]), s3 = __ldg(&g_csrc[e + 3]);
        int s4 = __ldg(&g_csrc[e + 4]), s5 = __ldg(&g_csrc[e + 5]);
        int s6 = __ldg(&g_csrc[e + 6]), s7 = __ldg(&g_csrc[e + 7]);
        float h0 = __half2float(__ldg(&g_h2[(srow + s0) * D_HID + lane]));
        float h1 = __half2float(__ldg(&g_h2[(srow + s1) * D_HID + lane]));
        float h2 = __half2float(__ldg(&g_h2[(srow + s2) * D_HID + lane]));
        float h3 = __half2float(__ldg(&g_h2[(srow + s3) * D_HID + lane]));
        float h4 = __half2float(__ldg(&g_h2[(srow + s4) * D_HID + lane]));
        float h5 = __half2float(__ldg(&g_h2[(srow + s5) * D_HID + lane]));
        float h6 = __half2float(__ldg(&g_h2[(srow + s6) * D_HID + lane]));
        float h7 = __half2float(__ldg(&g_h2[(srow + s7) * D_HID + lane]));
        acc += ((h0 + h1) + (h2 + h3)) + ((h4 + h5) + (h6 + h7));
    }
    for (; e < end; e++)
        acc += __half2float(__ldg(&g_h2[(srow + __ldg(&g_csrc[e])) * D_HID + lane]));
    float y = fmaxf(fmaf(acc, dn, __ldg(&b2[lane])), 0.f);
    const int* bat = side ? bat1 : bat0;
    int g = __ldg(&bat[n]);
    atomicAdd(&g_pool[(side * GG + g) * D_HID + lane], y);
    if (lane == 0) atomicAdd(&g_cnt[side * GG + g], 1.f);
}

// final MLP: [G,64] -> relu([G,32]) -> [G,1]   warp per graph
__global__ void __launch_bounds__(256) k_final(const float* __restrict__ fW1,
                                               const float* __restrict__ fb1,
                                               const float* __restrict__ fW2,
                                               const float* __restrict__ fb2,
                                               float* __restrict__ out) {
    int gt = blockIdx.x * blockDim.x + threadIdx.x;
    int g = gt >> 5, lane = gt & 31;
    if (g >= GG) return;
    float cl = 1.f / fmaxf(g_cnt[g], 1.f);
    float cr = 1.f / fmaxf(g_cnt[GG + g], 1.f);
    float pl = g_pool[g * D_HID + lane] * cl;
    float pr = g_pool[(GG + g) * D_HID + lane] * cr;
    float acc = __ldg(&fb1[lane]);
#pragma unroll
    for (int k = 0; k < D_HID; k++) {
        acc = fmaf(__shfl_sync(0xffffffffu, pl, k), __ldg(&fW1[k * D_HID + lane]), acc);
        acc = fmaf(__shfl_sync(0xffffffffu, pr, k), __ldg(&fW1[(D_HID + k) * D_HID + lane]), acc);
    }
    float v = fmaxf(acc, 0.f) * __ldg(&fW2[lane]);
#pragma unroll
    for (int o = 16; o > 0; o >>= 1) v += __shfl_down_sync(0xffffffffu, v, o);
    if (lane == 0) out[g] = v + __ldg(&fb2[0]);
}

// ---------------- launch ----------------

extern "C" void kernel_launch(void* const* d_in, const int* in_sizes, int n_in,
                              void* d_out, int out_size) {
    const int*   lhs_gid = (const int*)d_in[0];
    const float* lhs_par = (const float*)d_in[1];
    const int*   lhs_ei  = (const int*)d_in[2];
    const int*   lhs_b   = (const int*)d_in[3];
    const int*   rhs_gid = (const int*)d_in[4];
    const float* rhs_par = (const float*)d_in[5];
    const int*   rhs_ei  = (const int*)d_in[6];
    const int*   rhs_b   = (const int*)d_in[7];
    const float* emb = (const float*)d_in[8];
    const float* pW  = (const float*)d_in[9];
    const float* pb  = (const float*)d_in[10];
    const float* W1  = (const float*)d_in[11];
    const float* b1  = (const float*)d_in[12];
    const float* W2  = (const float*)d_in[13];
    const float* b2  = (const float*)d_in[14];
    const float* fW1 = (const float*)d_in[15];
    const float* fb1 = (const float*)d_in[16];
    const float* fW2 = (const float*)d_in[17];
    const float* fb2 = (const float*)d_in[18];
    float* out = (float*)d_out;

    const int TB = 256;
    k_zero<<<(2 * NN + TB - 1) / TB, TB>>>();
    k_count<<<(2 * EE + TB - 1) / TB, TB>>>(lhs_ei, rhs_ei);
    k_scan1<<<2 * SCAN_NB, SCAN_BS>>>();
    k_scan2<<<2, SCAN_BS>>>();
    k_scan3<<<2 * SCAN_NB, SCAN_BS>>>();
    k_scatter<<<(2 * EE + TB - 1) / TB, TB>>>(lhs_ei, rhs_ei);

    const int WBLK = (2 * NN * 32 + TB - 1) / TB;
    k_embed_mv16<<<WBLK, TB>>>(lhs_gid, lhs_par, rhs_gid, rhs_par, emb, pW, pb, W1);
    k_agg_mv32<<<WBLK, TB>>>(b1, W2);
    k_agg_pool<<<WBLK, TB>>>(b2, lhs_b, rhs_b);
    k_final<<<(GG * 32 + 255) / 256, 256>>>(fW1, fb1, fW2, fb2, out);
}